// round 13
// baseline (speedup 1.0000x reference)
#include <cuda_runtime.h>
#include <cuda_bf16.h>
#include <math.h>

#define BS_   64
#define NQ_   300
#define T_    1280            // 64 * 20 targets
#define ROWS_ (BS_ * NQ_)     // 19200
#define RPB_  16              // 1200 blocks, exact tiling
#define THREADS_ 320          // 1280 cols / 4 per thread

__device__ __forceinline__ float frcp(float x) {
    float r;
    asm("rcp.approx.f32 %0, %1;" : "=f"(r) : "f"(x));
    return r;
}

__global__ __launch_bounds__(THREADS_, 4)
void hungarian_cost_kernel(const float* __restrict__ logits,   // [ROWS_, 2]
                           const float* __restrict__ spans,    // [ROWS_, 2] (cx, w)
                           const float* __restrict__ tgt,      // [T_, 2]    (cx, w)
                           const float* __restrict__ refp,     // [ROWS_, 2]
                           float* __restrict__ out)            // [ROWS_, T_]
{
    // per-row constants: {cx, hw, rc, pad} — one LDS.128 per row
    __shared__ float4 s_row[RPB_];

    const int t    = threadIdx.x;          // owns columns 4t..4t+3
    const int row0 = blockIdx.x * RPB_;

    // ---- this thread's 4 target tuples: tcx and th = tw/2 ----
    const float4 ta = __ldg(reinterpret_cast<const float4*>(tgt) + 2 * t);
    const float4 tb = __ldg(reinterpret_cast<const float4*>(tgt) + 2 * t + 1);

    float tcx[4], th[4];
    tcx[0] = ta.x; th[0] = 0.5f * ta.y;
    tcx[1] = ta.z; th[1] = 0.5f * ta.w;
    tcx[2] = tb.x; th[2] = 0.5f * tb.y;
    tcx[3] = tb.z; th[3] = 0.5f * tb.w;

    // ---- cooperative per-row constants (threads 0..RPB_-1) ----
    if (t < RPB_) {
        const int r = row0 + t;
        const float l0 = __ldg(logits + 2 * r);
        const float l1 = __ldg(logits + 2 * r + 1);
        const float m  = fmaxf(l0, l1);
        const float e0 = __expf(l0 - m);
        const float e1 = __expf(l1 - m);
        const float p0 = __fdividef(e0, e0 + e1);  // softmax prob class 0

        const float cx = __ldg(spans + 2 * r);
        const float w  = __ldg(spans + 2 * r + 1);
        const float hw = 0.5f * w;
        const float x1 = cx - hw;
        const float x2 = cx + hw;

        const float r0 = __ldg(refp + 2 * r);
        const float r1 = __ldg(refp + 2 * r + 1);
        const float d0 = fabsf(x1 - r0);
        const float d1 = fabsf(x2 - r1);
        const float cref = sqrtf(fmaf(d0, d0, d1 * d1));

        // rc = cost_reference - class_prob   (NO +1: in 1D, giou = ri/enc exactly)
        s_row[t] = make_float4(cx, hw, cref - p0, 0.0f);
    }
    __syncthreads();

    float4* op = reinterpret_cast<float4*>(out + (size_t)row0 * T_) + t;

#pragma unroll 4
    for (int rr = 0; rr < RPB_; ++rr) {
        const float4 rd = s_row[rr];
        const float cx  = rd.x;
        const float hw  = rd.y;
        const float rc  = rd.z;

        float v[4];
#pragma unroll
        for (int i = 0; i < 4; ++i) {
            // 1D GIoU closed form: giou = ri/enc = (hs - M)/(hs + M)
            //   M  = max(|cx-tcx|, |hw-th|)
            //   hs = hw + th
            const float dc  = cx - tcx[i];                      // FADD
            const float e   = hw - th[i];                       // FADD
            const float hs  = hw + th[i];                       // FADD
            const float M   = fmaxf(fabsf(dc), fabsf(e));       // FMNMX (free abs)
            const float num = hs - M;                           // FADD (= ri, scaled)
            const float den = hs + M;                           // FADD (= enc, same scale)
            const float r   = frcp(den);                        // MUFU.RCP
            // L1 span: |cx-tcx| + |w-tw| = |dc| + 2|e|
            const float base = fmaf(2.0f, fabsf(e), fabsf(dc)); // FFMA
            const float bf   = base + rc;                       // FADD
            // v = base + rc - giou = bf - num/den
            v[i] = fmaf(-num, r, bf);                           // FFMA
        }

        *op = make_float4(v[0], v[1], v[2], v[3]);
        op += T_ / 4;
    }
}

extern "C" void kernel_launch(void* const* d_in, const int* in_sizes, int n_in,
                              void* d_out, int out_size) {
    const float* logits = (const float*)d_in[0];  // pred_logits [64,300,2]
    const float* spans  = (const float*)d_in[1];  // pred_spans  [64,300,2]
    const float* tgt    = (const float*)d_in[2];  // tgt_spans   [1280,2]
    const float* refp   = (const float*)d_in[3];  // ref_points  [64,300,2]
    float* out = (float*)d_out;                   // [64,300,1280] fp32

    hungarian_cost_kernel<<<ROWS_ / RPB_, THREADS_>>>(logits, spans, tgt, refp, out);
}

// round 14
// speedup vs baseline: 1.1220x; 1.1220x over previous
#include <cuda_runtime.h>
#include <cuda_bf16.h>
#include <math.h>

#define BS_   64
#define NQ_   300
#define T_    1280            // 64 * 20 targets
#define ROWS_ (BS_ * NQ_)     // 19200
#define RPB_  22              // 873 blocks <= 888 slots (148 SM x 6 CTA): one wave
#define NBLK_ ((ROWS_ + RPB_ - 1) / RPB_)   // 873
#define THREADS_ 320          // 1280 cols / 4 per thread

__device__ __forceinline__ float frcp(float x) {
    float r;
    asm("rcp.approx.f32 %0, %1;" : "=f"(r) : "f"(x));
    return r;
}

__device__ __forceinline__ float4 cost4(const float4 rd,
                                        const float* tcx, const float* th) {
    const float cx = rd.x, hw = rd.y, rc = rd.z;
    float v[4];
#pragma unroll
    for (int i = 0; i < 4; ++i) {
        // 1D GIoU closed form: giou = (hs - M)/(hs + M),
        //   M = max(|cx-tcx|, |hw-th|), hs = hw + th
        const float dc  = cx - tcx[i];
        const float e   = hw - th[i];
        const float hs  = hw + th[i];
        const float M   = fmaxf(fabsf(dc), fabsf(e));
        const float num = hs - M;
        const float den = hs + M;
        const float r   = frcp(den);
        const float base = fmaf(2.0f, fabsf(e), fabsf(dc));  // L1 span
        const float bf   = base + rc;
        v[i] = fmaf(-num, r, bf);
    }
    return make_float4(v[0], v[1], v[2], v[3]);
}

__global__ __launch_bounds__(THREADS_, 6)   // 32-reg cap -> 6 CTAs/SM, 60 warps
void hungarian_cost_kernel(const float* __restrict__ logits,   // [ROWS_, 2]
                           const float* __restrict__ spans,    // [ROWS_, 2] (cx, w)
                           const float* __restrict__ tgt,      // [T_, 2]    (cx, w)
                           const float* __restrict__ refp,     // [ROWS_, 2]
                           float* __restrict__ out)            // [ROWS_, T_]
{
    __shared__ float4 s_row[RPB_];   // {cx, hw, rc, pad}

    const int t    = threadIdx.x;          // owns columns 4t..4t+3
    const int row0 = blockIdx.x * RPB_;

    // ---- this thread's 4 target tuples: tcx, th = tw/2 ----
    const float4 ta = __ldg(reinterpret_cast<const float4*>(tgt) + 2 * t);
    const float4 tb = __ldg(reinterpret_cast<const float4*>(tgt) + 2 * t + 1);

    float tcx[4], th[4];
    tcx[0] = ta.x; th[0] = 0.5f * ta.y;
    tcx[1] = ta.z; th[1] = 0.5f * ta.w;
    tcx[2] = tb.x; th[2] = 0.5f * tb.y;
    tcx[3] = tb.z; th[3] = 0.5f * tb.w;

    // ---- cooperative per-row constants (threads 0..RPB_-1) ----
    if (t < RPB_) {
        const int r = row0 + t;
        if (r < ROWS_) {
            const float l0 = __ldg(logits + 2 * r);
            const float l1 = __ldg(logits + 2 * r + 1);
            const float m  = fmaxf(l0, l1);
            const float e0 = __expf(l0 - m);
            const float e1 = __expf(l1 - m);
            const float p0 = __fdividef(e0, e0 + e1);  // softmax prob class 0

            const float cx = __ldg(spans + 2 * r);
            const float w  = __ldg(spans + 2 * r + 1);
            const float hw = 0.5f * w;
            const float x1 = cx - hw;
            const float x2 = cx + hw;

            const float r0 = __ldg(refp + 2 * r);
            const float r1 = __ldg(refp + 2 * r + 1);
            const float d0 = fabsf(x1 - r0);
            const float d1 = fabsf(x2 - r1);
            const float cref = sqrtf(fmaf(d0, d0, d1 * d1));

            // rc = cost_reference - class_prob  (giou = ri/enc exactly in 1D)
            s_row[t] = make_float4(cx, hw, cref - p0, 0.0f);
        }
    }
    __syncthreads();

    float4* const op = reinterpret_cast<float4*>(out + (size_t)row0 * T_) + t;

    if (row0 + RPB_ <= ROWS_) {
        // interior block: fully unrolled, immediate offsets, no guards
#pragma unroll
        for (int rr = 0; rr < RPB_; ++rr) {
            op[rr * (T_ / 4)] = cost4(s_row[rr], tcx, th);
        }
    } else {
        // tail block (only block 872): per-row guard
#pragma unroll
        for (int rr = 0; rr < RPB_; ++rr) {
            if (row0 + rr < ROWS_) {
                op[rr * (T_ / 4)] = cost4(s_row[rr], tcx, th);
            }
        }
    }
}

extern "C" void kernel_launch(void* const* d_in, const int* in_sizes, int n_in,
                              void* d_out, int out_size) {
    const float* logits = (const float*)d_in[0];  // pred_logits [64,300,2]
    const float* spans  = (const float*)d_in[1];  // pred_spans  [64,300,2]
    const float* tgt    = (const float*)d_in[2];  // tgt_spans   [1280,2]
    const float* refp   = (const float*)d_in[3];  // ref_points  [64,300,2]
    float* out = (float*)d_out;                   // [64,300,1280] fp32

    hungarian_cost_kernel<<<NBLK_, THREADS_>>>(logits, spans, tgt, refp, out);
}